// round 2
// baseline (speedup 1.0000x reference)
#include <cuda_runtime.h>
#include <cstdint>

#define BATCH 8
#define NA 3
#define NC 80
#define HH 160
#define WW 160
#define HW 25600      // HH*WW
#define NPB 76800     // NA*HW candidates per batch
#define TOPKK 100
#define MTARGET 2048  // E1 target size per batch
#define NBIN 4096
#define CAP 4096

typedef unsigned long long u64;
typedef unsigned int u32;

// ---------------- static device scratch ----------------
__device__ float g_ub[BATCH * NPB];      // sigmoid(obj)*sigmoid(qual) upper bound
__device__ u64  g_keys[BATCH * NPB];     // evaluated score keys, compacted per batch
__device__ int  g_cidx[BATCH * NPB];     // candidate pixel indices (E1 then E2)
__device__ u32  g_ubhist[BATCH * NBIN];  // histogram of ub float bits >> 18
__device__ u32  g_schist[BATCH * NBIN];  // histogram of E1 score bits >> 18
__device__ int  g_cnt1[BATCH];
__device__ int  g_cnt2[BATCH];
__device__ u32  g_T1[BATCH];             // ub bin threshold for E1
__device__ u32  g_T2[BATCH];             // score bin lower bound for top-100

__device__ __forceinline__ float fsig(float x) { return 1.0f / (1.0f + __expf(-x)); }

// ---------------- K0: zero per-launch state ----------------
__global__ void initK() {
    int i = blockIdx.x * blockDim.x + threadIdx.x;
    if (i < BATCH * NBIN) { g_ubhist[i] = 0; g_schist[i] = 0; }
    if (i < BATCH) { g_cnt1[i] = 0; g_cnt2[i] = 0; }
}

// ---------------- K1: upper bound + histogram (reads only obj/qual) ----------------
__global__ void __launch_bounds__(256) ubK(const float* __restrict__ obj,
                                           const float* __restrict__ qual) {
    __shared__ u32 hist[NBIN];
    for (int j = threadIdx.x; j < NBIN; j += 256) hist[j] = 0;
    __syncthreads();

    int g0 = blockIdx.x * 1024 + threadIdx.x * 4;   // flat over BATCH*NPB
    int b = g0 / NPB;
    float4 o4 = *reinterpret_cast<const float4*>(obj + g0);
    float4 q4 = *reinterpret_cast<const float4*>(qual + g0);
    float u0 = 1.0f / ((1.0f + __expf(-o4.x)) * (1.0f + __expf(-q4.x)));
    float u1 = 1.0f / ((1.0f + __expf(-o4.y)) * (1.0f + __expf(-q4.y)));
    float u2 = 1.0f / ((1.0f + __expf(-o4.z)) * (1.0f + __expf(-q4.z)));
    float u3 = 1.0f / ((1.0f + __expf(-o4.w)) * (1.0f + __expf(-q4.w)));
    *reinterpret_cast<float4*>(g_ub + g0) = make_float4(u0, u1, u2, u3);

    atomicAdd(&hist[__float_as_uint(u0) >> 18], 1u);
    atomicAdd(&hist[__float_as_uint(u1) >> 18], 1u);
    atomicAdd(&hist[__float_as_uint(u2) >> 18], 1u);
    atomicAdd(&hist[__float_as_uint(u3) >> 18], 1u);
    __syncthreads();

    u32* gh = g_ubhist + b * NBIN;
    for (int j = threadIdx.x; j < NBIN; j += 256) {
        u32 v = hist[j];
        if (v) atomicAdd(&gh[j], v);
    }
}

// ---------------- K2/K5: boundary-bin selection (which=0: ub/MTARGET, which=1: score/TOPKK) --------
__global__ void __launch_bounds__(256) selK(int which) {
    int b = blockIdx.x, t = threadIdx.x;
    const u32* gh = (which ? g_schist : g_ubhist) + b * NBIN;
    int K = which ? TOPKK : MTARGET;
    __shared__ u32 h[NBIN];
    __shared__ u32 csum[256];
    for (int j = t; j < NBIN; j += 256) h[j] = gh[j];
    __syncthreads();
    u32 s = 0;
#pragma unroll
    for (int q = 0; q < 16; q++) s += h[t * 16 + q];
    csum[t] = s;
    __syncthreads();
    for (int d = 1; d < 256; d <<= 1) {
        u32 v = (t + d < 256) ? csum[t + d] : 0u;
        __syncthreads();
        csum[t] += v;
        __syncthreads();
    }
    u32 above = (t < 255) ? csum[t + 1] : 0u;
    if ((int)csum[t] >= K && (int)above < K) {   // exactly one thread
        u32 cum = above;
        int d;
        for (d = t * 16 + 15;; d--) {
            if ((int)(cum + h[d]) >= K) break;
            cum += h[d];
        }
        if (which) g_T2[b] = (u32)d; else g_T1[b] = (u32)d;
    }
}

// ---------------- K3: collect E1 (ub bin >= T1) ----------------
__global__ void __launch_bounds__(256) collect1K() {
    int g0 = blockIdx.x * 1024 + threadIdx.x * 4;
    int b = g0 / NPB;
    int i = g0 - b * NPB;
    u32 T1 = g_T1[b];
    float4 u4 = *reinterpret_cast<const float4*>(g_ub + g0);
    float us[4] = {u4.x, u4.y, u4.z, u4.w};
#pragma unroll
    for (int j = 0; j < 4; j++) {
        if ((__float_as_uint(us[j]) >> 18) >= T1) {
            int pos = atomicAdd(&g_cnt1[b], 1);
            g_cidx[b * NPB + pos] = i + j;
        }
    }
}

// ---------------- shared: evaluate one candidate (warp-collective) ----------------
__device__ __forceinline__ u64 evalCand(const float* __restrict__ cls, int b, int idx, int lane) {
    int a = idx / HW;
    int pix = idx - a * HW;
    const float* cp = cls + (size_t)(b * NA + a) * NC * HW + pix;
    float m = -3.4e38f;
    for (int c = lane; c < NC; c += 32) m = fmaxf(m, cp[(size_t)c * HW]);
#pragma unroll
    for (int off = 16; off; off >>= 1) m = fmaxf(m, __shfl_xor_sync(0xffffffffu, m, off));
    float ub = g_ub[b * NPB + idx];
    // IEEE division, denom >= 1  =>  score <= ub bitwise: pruning invariant
    float score = __fdiv_rn(ub, 1.0f + __expf(-m));
    return ((u64)__float_as_uint(score) << 17) | (u32)(NPB - 1 - idx);
}

// ---------------- K4: evaluate E1, build score histogram ----------------
__global__ void __launch_bounds__(256) eval1K(const float* __restrict__ cls) {
    int b = blockIdx.y;
    int warp = blockIdx.x * 8 + (threadIdx.x >> 5);
    int lane = threadIdx.x & 31;
    int n = g_cnt1[b];
    for (int j = warp; j < n; j += 64 * 8) {
        int idx = g_cidx[b * NPB + j];
        u64 key = evalCand(cls, b, idx, lane);
        if (lane == 0) {
            g_keys[b * NPB + j] = key;
            atomicAdd(&g_schist[b * NBIN + (u32)(key >> 35)], 1u);
        }
    }
}

// ---------------- K6: collect E2 = { T2 <= ub_bin < T1 } ----------------
__global__ void __launch_bounds__(256) collect2K() {
    int g0 = blockIdx.x * 1024 + threadIdx.x * 4;
    int b = g0 / NPB;
    int i = g0 - b * NPB;
    u32 T1 = g_T1[b];
    u32 T2 = g_T2[b];
    int c1 = g_cnt1[b];
    float4 u4 = *reinterpret_cast<const float4*>(g_ub + g0);
    float us[4] = {u4.x, u4.y, u4.z, u4.w};
#pragma unroll
    for (int j = 0; j < 4; j++) {
        u32 bin = __float_as_uint(us[j]) >> 18;
        if (bin >= T2 && bin < T1) {
            int pos = c1 + atomicAdd(&g_cnt2[b], 1);
            g_cidx[b * NPB + pos] = i + j;
        }
    }
}

// ---------------- K7: eval E2 + per-batch top-100 + decode ----------------
__global__ void __launch_bounds__(1024) finalK(const float* __restrict__ box,
                                               const float* __restrict__ cls,
                                               const float* __restrict__ anch,
                                               float* __restrict__ out) {
    int b = blockIdx.x, tid = threadIdx.x;
    int lane = tid & 31, warp = tid >> 5;
    __shared__ u64 scand[CAP];                       // 32 KB; aliased by hist/csum in slow path
    __shared__ int s_cnt, s_d, s_locked, s_bucket;

    int c1 = g_cnt1[b], c2 = g_cnt2[b];

    // evaluate E2 (usually empty)
    for (int j = warp; j < c2; j += 32) {
        int idx = g_cidx[b * NPB + c1 + j];
        u64 key = evalCand(cls, b, idx, lane);
        if (lane == 0) g_keys[b * NPB + c1 + j] = key;
    }
    __syncthreads();

    int M = c1 + c2;
    const u64* keys = g_keys + (size_t)b * NPB;

    // quick filter: keep keys with score bin >= T2 (>=100 of them exist by construction)
    u32 T2v = g_T2[b];
    if (tid == 0) s_cnt = 0;
    __syncthreads();
    for (int j = tid; j < M; j += 1024) {
        u64 k = keys[j];
        if ((u32)(k >> 35) >= T2v) {
            int pos = atomicAdd(&s_cnt, 1);
            if (pos < CAP) scand[pos] = k;
        }
    }
    __syncthreads();
    int C = s_cnt;

    if (C > CAP) {
        // exact slow path: 12-bit radix refinement over compacted keys (keys < 2^47)
        u32* hist = reinterpret_cast<u32*>(scand);
        u32* csum = reinterpret_cast<u32*>(scand + 2048);
        u64 prefixVal = 0;
        int locked = 0, shift = 35, bucket = 0;
        for (int lvl = 0; lvl < 3; lvl++) {
            shift = 35 - 12 * lvl;
            __syncthreads();
            for (int j = tid; j < NBIN; j += 1024) hist[j] = 0;
            __syncthreads();
            u64 maskAbove = ~((((u64)1) << (shift + 12)) - 1);
            for (int j = tid; j < M; j += 1024) {
                u64 k = keys[j];
                if ((k & maskAbove) == prefixVal)
                    atomicAdd(&hist[(u32)(k >> shift) & (NBIN - 1)], 1u);
            }
            __syncthreads();
            u32 s = 0;
#pragma unroll
            for (int q = 0; q < 4; q++) s += hist[tid * 4 + q];
            csum[tid] = s;
            __syncthreads();
            for (int d = 1; d < 1024; d <<= 1) {
                u32 v = (tid + d < 1024) ? csum[tid + d] : 0u;
                __syncthreads();
                csum[tid] += v;
                __syncthreads();
            }
            u32 above = (tid < 1023) ? csum[tid + 1] : 0u;
            if (locked + (int)csum[tid] >= TOPKK && locked + (int)above < TOPKK) {
                u32 cum = above;
                int d;
                for (d = tid * 4 + 3;; d--) {
                    if (locked + (int)(cum + hist[d]) >= TOPKK) break;
                    cum += hist[d];
                }
                s_d = d; s_locked = locked + (int)cum; s_bucket = (int)hist[d];
            }
            __syncthreads();
            locked = s_locked;
            prefixVal |= ((u64)s_d) << shift;
            bucket = s_bucket;
            __syncthreads();
            if (locked + bucket <= CAP) break;   // guaranteed at shift=11 (low 11 bits distinct)
        }
        if (tid == 0) s_cnt = 0;
        __syncthreads();
        u64 thr = prefixVal >> shift;
        for (int j = tid; j < M; j += 1024) {
            u64 k = keys[j];
            if ((k >> shift) >= thr) {
                int pos = atomicAdd(&s_cnt, 1);
                scand[pos] = k;
            }
        }
        __syncthreads();
        C = s_cnt;
    }

    // bitonic sort descending (pad with 0)
    int npow = 128;
    while (npow < C) npow <<= 1;
    for (int j = C + tid; j < npow; j += 1024) scand[j] = 0ull;
    __syncthreads();
    for (int k = 2; k <= npow; k <<= 1) {
        for (int j = k >> 1; j > 0; j >>= 1) {
            for (int i = tid; i < npow; i += 1024) {
                int ixj = i ^ j;
                if (ixj > i) {
                    u64 A = scand[i], Bv = scand[ixj];
                    bool sw = ((i & k) == 0) ? (A < Bv) : (A > Bv);
                    if (sw) { scand[i] = Bv; scand[ixj] = A; }
                }
            }
            __syncthreads();
        }
    }

    // winners: warp per rank — 80-class argmax + box decode
    for (int r = warp; r < TOPKK; r += 32) {
        u64 k = scand[r];
        u32 sb = (u32)(k >> 17);
        int idx = NPB - 1 - (int)(k & 0x1FFFFu);
        int a = idx / HW;
        int pix = idx - a * HW;
        int y = pix / WW;
        int x = pix - y * WW;

        const float* cp = cls + (size_t)(b * NA + a) * NC * HW + pix;
        float bv = -3.4e38f;
        int bc = 0;
        for (int c = lane; c < NC; c += 32) {
            float v = cp[(size_t)c * HW];
            if (v > bv) { bv = v; bc = c; }
        }
#pragma unroll
        for (int off = 16; off; off >>= 1) {
            float ov = __shfl_xor_sync(0xffffffffu, bv, off);
            int oc = __shfl_xor_sync(0xffffffffu, bc, off);
            if (ov > bv || (ov == bv && oc < bc)) { bv = ov; bc = oc; }
        }
        if (lane == 0) {
            const float* bp = box + (size_t)(b * NA + a) * 4 * HW + pix;
            float tx = bp[0];
            float ty = bp[(size_t)HW];
            float tw = bp[2 * (size_t)HW];
            float th = bp[3 * (size_t)HW];
            float aw = anch[a * 2 + 0];
            float ah = anch[a * 2 + 1];
            float cx = (fsig(tx) + (float)x) / (float)WW;
            float cy = (fsig(ty) + (float)y) / (float)HH;
            float spw = fmaxf(tw, 0.0f) + log1pf(__expf(-fabsf(tw)));
            float sph = fmaxf(th, 0.0f) + log1pf(__expf(-fabsf(th)));
            float* o = out + ((size_t)b * TOPKK + r) * 6;
            o[0] = __uint_as_float(sb);
            o[1] = (float)bc;
            o[2] = cx;
            o[3] = cy;
            o[4] = aw * spw;
            o[5] = ah * sph;
        }
    }
}

// ---------------- launch ----------------
extern "C" void kernel_launch(void* const* d_in, const int* in_sizes, int n_in,
                              void* d_out, int out_size) {
    const float* box  = (const float*)d_in[0];
    const float* obj  = (const float*)d_in[1];
    const float* qual = (const float*)d_in[2];
    const float* cls  = (const float*)d_in[3];
    const float* anch = (const float*)d_in[4];
    int seen = 0;
    for (int i = 0; i < n_in; i++) {
        int s = in_sizes[i];
        if (s == BATCH * NA * 4 * HW) box = (const float*)d_in[i];
        else if (s == BATCH * NA * NC * HW) cls = (const float*)d_in[i];
        else if (s == NA * 2) anch = (const float*)d_in[i];
        else if (s == BATCH * NA * HW) {
            if (seen == 0) obj = (const float*)d_in[i];
            else qual = (const float*)d_in[i];
            seen++;
        }
    }
    float* out = (float*)d_out;

    initK<<<(BATCH * NBIN + 255) / 256, 256>>>();
    ubK<<<600, 256>>>(obj, qual);
    selK<<<BATCH, 256>>>(0);
    collect1K<<<600, 256>>>();
    eval1K<<<dim3(64, BATCH), 256>>>(cls);
    selK<<<BATCH, 256>>>(1);
    collect2K<<<600, 256>>>();
    finalK<<<BATCH, 1024>>>(box, cls, anch, out);
}

// round 4
// speedup vs baseline: 1.4780x; 1.4780x over previous
#include <cuda_runtime.h>
#include <cstdint>

#define BATCH 8
#define NA 3
#define NC 80
#define HH 160
#define WW 160
#define HW 25600      // HH*WW
#define NPB 76800     // NA*HW candidates per batch
#define TOPKK 100
#define MTARGET 2048  // E1 target size per batch
#define NBIN 4096
#define CAP 4096

typedef unsigned long long u64;
typedef unsigned int u32;

// ---------------- static device scratch (zero-initialized at load; finalK re-zeros) -------------
__device__ float g_ub[BATCH * NPB];      // sigmoid(obj)*sigmoid(qual) upper bound
__device__ u64  g_keys[BATCH * NPB];     // evaluated score keys per batch (E1 then E2)
__device__ u32  g_ubhist[BATCH * NBIN];  // histogram of ub float bits >> 18
__device__ u32  g_schist[BATCH * NBIN];  // histogram of E1 score bits (key >> 35)
__device__ int  g_cnt1[BATCH];           // evaluated E1 count
__device__ u32  g_T1[BATCH];             // ub bin threshold defining E1

__device__ __forceinline__ float fsig(float x) { return 1.0f / (1.0f + __expf(-x)); }

// warp-collective: max class logit -> exact score key for candidate idx
__device__ __forceinline__ u64 evalCand(const float* __restrict__ cls, int b, int idx, int lane) {
    int a = idx / HW;
    int pix = idx - a * HW;
    const float* cp = cls + (size_t)(b * NA + a) * NC * HW + pix;
    float m = fmaxf(cp[(size_t)lane * HW], cp[(size_t)(lane + 32) * HW]);
    if (lane < 16) m = fmaxf(m, cp[(size_t)(lane + 64) * HW]);
#pragma unroll
    for (int off = 16; off; off >>= 1) m = fmaxf(m, __shfl_xor_sync(0xffffffffu, m, off));
    float ub = g_ub[b * NPB + idx];
    // IEEE division with denom >= 1  =>  score <= ub bitwise (pruning invariant)
    float score = __fdiv_rn(ub, 1.0f + __expf(-m));
    return ((u64)__float_as_uint(score) << 17) | (u32)(NPB - 1 - idx);
}

// ---------------- K1: upper bound + per-batch histogram ----------------
__global__ void __launch_bounds__(256) ubK(const float* __restrict__ obj,
                                           const float* __restrict__ qual) {
    __shared__ u32 hist[NBIN];
    for (int j = threadIdx.x; j < NBIN; j += 256) hist[j] = 0;
    __syncthreads();

    int bid = blockIdx.x;
    int b = bid / 75;
    int g0 = b * NPB + (bid - b * 75) * 1024 + threadIdx.x * 4;
    float4 o4 = *reinterpret_cast<const float4*>(obj + g0);
    float4 q4 = *reinterpret_cast<const float4*>(qual + g0);
    float u0 = 1.0f / ((1.0f + __expf(-o4.x)) * (1.0f + __expf(-q4.x)));
    float u1 = 1.0f / ((1.0f + __expf(-o4.y)) * (1.0f + __expf(-q4.y)));
    float u2 = 1.0f / ((1.0f + __expf(-o4.z)) * (1.0f + __expf(-q4.z)));
    float u3 = 1.0f / ((1.0f + __expf(-o4.w)) * (1.0f + __expf(-q4.w)));
    *reinterpret_cast<float4*>(g_ub + g0) = make_float4(u0, u1, u2, u3);

    atomicAdd(&hist[__float_as_uint(u0) >> 18], 1u);
    atomicAdd(&hist[__float_as_uint(u1) >> 18], 1u);
    atomicAdd(&hist[__float_as_uint(u2) >> 18], 1u);
    atomicAdd(&hist[__float_as_uint(u3) >> 18], 1u);
    __syncthreads();

    u32* gh = g_ubhist + b * NBIN;
    for (int j = threadIdx.x; j < NBIN; j += 256) {
        u32 v = hist[j];
        if (v) atomicAdd(&gh[j], v);
    }
}

// ---------------- K2: per-batch T1 (boundary ub bin for ~MTARGET survivors) ----------------
__global__ void __launch_bounds__(256) selT1K() {
    int b = blockIdx.x, t = threadIdx.x;
    const u32* gh = g_ubhist + b * NBIN;
    __shared__ u32 h[NBIN];
    __shared__ u32 csum[256];
    for (int j = t; j < NBIN; j += 256) h[j] = gh[j];
    __syncthreads();
    u32 s = 0;
#pragma unroll
    for (int q = 0; q < 16; q++) s += h[t * 16 + q];
    csum[t] = s;
    __syncthreads();
    for (int d = 1; d < 256; d <<= 1) {
        u32 v = (t + d < 256) ? csum[t + d] : 0u;
        __syncthreads();
        csum[t] += v;
        __syncthreads();
    }
    u32 above = (t < 255) ? csum[t + 1] : 0u;
    if ((int)csum[t] >= MTARGET && (int)above < MTARGET) {   // exactly one thread
        u32 cum = above;
        int d;
        for (d = t * 16 + 15;; d--) {
            if ((int)(cum + h[d]) >= MTARGET) break;
            cum += h[d];
        }
        g_T1[b] = (u32)d;
    }
}

// ---------------- K3: collect E1 (block-aggregated) + evaluate + score hist ----------------
__global__ void __launch_bounds__(256) collEvalK(const float* __restrict__ cls) {
    __shared__ int sbuf[1024];
    __shared__ int s_n, s_pos;
    int tid = threadIdx.x;
    if (tid == 0) { s_n = 0; s_pos = 0; }
    __syncthreads();

    int bid = blockIdx.x;
    int b = bid / 75;
    int i0 = (bid - b * 75) * 1024 + tid * 4;
    u32 T1 = g_T1[b];
    float4 u4 = *reinterpret_cast<const float4*>(g_ub + b * NPB + i0);
    float us[4] = {u4.x, u4.y, u4.z, u4.w};
#pragma unroll
    for (int j = 0; j < 4; j++) {
        if ((__float_as_uint(us[j]) >> 18) >= T1) {
            int p = atomicAdd(&s_n, 1);         // shared atomic: cheap
            sbuf[p] = i0 + j;
        }
    }
    __syncthreads();
    if (tid == 0 && s_n) s_pos = atomicAdd(&g_cnt1[b], s_n);   // ONE global atomic per block
    __syncthreads();

    int n = s_n, pos = s_pos;
    int lane = tid & 31, warp = tid >> 5;
    for (int j = warp; j < n; j += 8) {
        u64 key = evalCand(cls, b, sbuf[j], lane);
        if (lane == 0) {
            g_keys[(size_t)b * NPB + pos + j] = key;
            atomicAdd(&g_schist[b * NBIN + (u32)(key >> 35)], 1u);
        }
    }
}

// ---------------- K4: T2 select, optional E2, filter, sort, decode, reset scratch ----------------
__global__ void __launch_bounds__(1024) finalK(const float* __restrict__ box,
                                               const float* __restrict__ cls,
                                               const float* __restrict__ anch,
                                               float* __restrict__ out) {
    int b = blockIdx.x, tid = threadIdx.x;
    int lane = tid & 31, warp = tid >> 5;
    __shared__ u64 scand[CAP];                   // 32 KB; aliased: T2 hist, then E2 ebuf, then cands
    __shared__ u32 csum[1024];                   // 4 KB
    __shared__ int s_cnt, s_d, s_locked, s_bucket, s_en, s_c2;

    int c1 = g_cnt1[b];
    u32* h = reinterpret_cast<u32*>(scand);      // alias #1: schist view (16 KB)
    int* ebuf = reinterpret_cast<int*>(scand);   // alias #2: E2 tile buffer (16 KB), after T2 done

    // ---- T2: bin of the 100th-best evaluated score ----
    for (int j = tid; j < NBIN; j += 1024) h[j] = g_schist[b * NBIN + j];
    __syncthreads();
    u32 s = 0;
#pragma unroll
    for (int q = 0; q < 4; q++) s += h[tid * 4 + q];
    csum[tid] = s;
    __syncthreads();
    for (int d = 1; d < 1024; d <<= 1) {
        u32 v = (tid + d < 1024) ? csum[tid + d] : 0u;
        __syncthreads();
        csum[tid] += v;
        __syncthreads();
    }
    u32 above0 = (tid < 1023) ? csum[tid + 1] : 0u;
    if ((int)csum[tid] >= TOPKK && (int)above0 < TOPKK) {
        u32 cum = above0;
        int d;
        for (d = tid * 4 + 3;; d--) {
            if ((int)(cum + h[d]) >= TOPKK) break;
            cum += h[d];
        }
        s_d = d;
    }
    __syncthreads();
    u32 T2v = (u32)s_d;
    u32 T1v = g_T1[b];

    // ---- E2: pixels with ub bin in [T2, T1) — usually empty (hist alias dead now) ----
    int c2 = 0;
    if (T2v < T1v) {
        if (tid == 0) s_c2 = 0;
        __syncthreads();
        for (int base = 0; base < NPB; base += 4096) {
            if (tid == 0) s_en = 0;
            __syncthreads();
            int i = base + tid * 4;
            if (i < NPB) {
                float4 u4 = *reinterpret_cast<const float4*>(g_ub + b * NPB + i);
                float us[4] = {u4.x, u4.y, u4.z, u4.w};
#pragma unroll
                for (int j = 0; j < 4; j++) {
                    u32 bin = __float_as_uint(us[j]) >> 18;
                    if (bin >= T2v && bin < T1v) {
                        int p = atomicAdd(&s_en, 1);
                        ebuf[p] = i + j;
                    }
                }
            }
            __syncthreads();
            int en = s_en, c2b = s_c2;
            for (int j = warp; j < en; j += 32) {
                u64 key = evalCand(cls, b, ebuf[j], lane);
                if (lane == 0) g_keys[(size_t)b * NPB + c1 + c2b + j] = key;
            }
            __syncthreads();
            if (tid == 0) s_c2 = c2b + en;
            __syncthreads();
        }
        c2 = s_c2;
    }
    int M = c1 + c2;
    const u64* keys = g_keys + (size_t)b * NPB;

    // ---- filter keys with score bin >= T2 into smem (>=100 exist by construction) ----
    __syncthreads();                              // ebuf alias dead; scand becomes candidate array
    if (tid == 0) s_cnt = 0;
    __syncthreads();
    for (int j = tid; j < M; j += 1024) {
        u64 k = keys[j];
        if ((u32)(k >> 35) >= T2v) {
            int pos = atomicAdd(&s_cnt, 1);
            if (pos < CAP) scand[pos] = k;
        }
    }
    __syncthreads();
    int C = s_cnt;

    if (C > CAP) {
        // exact slow path: 12-bit radix refinement over all M keys (keys < 2^47)
        u32* hist = reinterpret_cast<u32*>(scand);
        u64 prefixVal = 0;
        int locked = 0, shift = 35, bucket = 0;
        for (int lvl = 0; lvl < 3; lvl++) {
            shift = 35 - 12 * lvl;
            __syncthreads();
            for (int j = tid; j < NBIN; j += 1024) hist[j] = 0;
            __syncthreads();
            u64 maskAbove = ~((((u64)1) << (shift + 12)) - 1);
            for (int j = tid; j < M; j += 1024) {
                u64 k = keys[j];
                if ((k & maskAbove) == prefixVal)
                    atomicAdd(&hist[(u32)(k >> shift) & (NBIN - 1)], 1u);
            }
            __syncthreads();
            u32 ss = 0;
#pragma unroll
            for (int q = 0; q < 4; q++) ss += hist[tid * 4 + q];
            csum[tid] = ss;
            __syncthreads();
            for (int d = 1; d < 1024; d <<= 1) {
                u32 v = (tid + d < 1024) ? csum[tid + d] : 0u;
                __syncthreads();
                csum[tid] += v;
                __syncthreads();
            }
            u32 above = (tid < 1023) ? csum[tid + 1] : 0u;
            if (locked + (int)csum[tid] >= TOPKK && locked + (int)above < TOPKK) {
                u32 cum = above;
                int d;
                for (d = tid * 4 + 3;; d--) {
                    if (locked + (int)(cum + hist[d]) >= TOPKK) break;
                    cum += hist[d];
                }
                s_d = d; s_locked = locked + (int)cum; s_bucket = (int)hist[d];
            }
            __syncthreads();
            locked = s_locked;
            prefixVal |= ((u64)s_d) << shift;
            bucket = s_bucket;
            __syncthreads();
            if (locked + bucket <= CAP) break;   // guaranteed by shift=11 (low bits distinct)
        }
        if (tid == 0) s_cnt = 0;
        __syncthreads();
        u64 thr = prefixVal >> shift;
        for (int j = tid; j < M; j += 1024) {
            u64 k = keys[j];
            if ((k >> shift) >= thr) {
                int pos = atomicAdd(&s_cnt, 1);
                scand[pos] = k;
            }
        }
        __syncthreads();
        C = s_cnt;
    }

    // ---- bitonic sort descending (pad with 0) ----
    int npow = 128;
    while (npow < C) npow <<= 1;
    for (int j = C + tid; j < npow; j += 1024) scand[j] = 0ull;
    __syncthreads();
    for (int k = 2; k <= npow; k <<= 1) {
        for (int j = k >> 1; j > 0; j >>= 1) {
            for (int i = tid; i < npow; i += 1024) {
                int ixj = i ^ j;
                if (ixj > i) {
                    u64 A = scand[i], Bv = scand[ixj];
                    bool sw = ((i & k) == 0) ? (A < Bv) : (A > Bv);
                    if (sw) { scand[i] = Bv; scand[ixj] = A; }
                }
            }
            __syncthreads();
        }
    }

    // ---- winners: warp per rank — 80-class argmax + box decode ----
    for (int r = warp; r < TOPKK; r += 32) {
        u64 k = scand[r];
        u32 sb = (u32)(k >> 17);
        int idx = NPB - 1 - (int)(k & 0x1FFFFu);
        int a = idx / HW;
        int pix = idx - a * HW;
        int y = pix / WW;
        int x = pix - y * WW;

        const float* cp = cls + (size_t)(b * NA + a) * NC * HW + pix;
        float bv = -3.4e38f;
        int bc = 0;
        for (int c = lane; c < NC; c += 32) {
            float v = cp[(size_t)c * HW];
            if (v > bv) { bv = v; bc = c; }
        }
#pragma unroll
        for (int off = 16; off; off >>= 1) {
            float ov = __shfl_xor_sync(0xffffffffu, bv, off);
            int oc = __shfl_xor_sync(0xffffffffu, bc, off);
            if (ov > bv || (ov == bv && oc < bc)) { bv = ov; bc = oc; }
        }
        if (lane == 0) {
            const float* bp = box + (size_t)(b * NA + a) * 4 * HW + pix;
            float tx = bp[0];
            float ty = bp[(size_t)HW];
            float tw = bp[2 * (size_t)HW];
            float th = bp[3 * (size_t)HW];
            float aw = anch[a * 2 + 0];
            float ah = anch[a * 2 + 1];
            float cx = (fsig(tx) + (float)x) / (float)WW;
            float cy = (fsig(ty) + (float)y) / (float)HH;
            float spw = fmaxf(tw, 0.0f) + log1pf(__expf(-fabsf(tw)));
            float sph = fmaxf(th, 0.0f) + log1pf(__expf(-fabsf(th)));
            float* o = out + ((size_t)b * TOPKK + r) * 6;
            o[0] = __uint_as_float(sb);
            o[1] = (float)bc;
            o[2] = cx;
            o[3] = cy;
            o[4] = aw * spw;
            o[5] = ah * sph;
        }
    }

    // ---- reset scratch for the next replay (device globals start zeroed on load) ----
    __syncthreads();
    u32* uh = g_ubhist + b * NBIN;
    u32* sh = g_schist + b * NBIN;
    for (int j = tid; j < NBIN; j += 1024) { uh[j] = 0; sh[j] = 0; }
    if (tid == 0) g_cnt1[b] = 0;
}

// ---------------- launch ----------------
extern "C" void kernel_launch(void* const* d_in, const int* in_sizes, int n_in,
                              void* d_out, int out_size) {
    const float* box  = (const float*)d_in[0];
    const float* obj  = (const float*)d_in[1];
    const float* qual = (const float*)d_in[2];
    const float* cls  = (const float*)d_in[3];
    const float* anch = (const float*)d_in[4];
    int seen = 0;
    for (int i = 0; i < n_in; i++) {
        int s = in_sizes[i];
        if (s == BATCH * NA * 4 * HW) box = (const float*)d_in[i];
        else if (s == BATCH * NA * NC * HW) cls = (const float*)d_in[i];
        else if (s == NA * 2) anch = (const float*)d_in[i];
        else if (s == BATCH * NA * HW) {
            if (seen == 0) obj = (const float*)d_in[i];
            else qual = (const float*)d_in[i];
            seen++;
        }
    }
    float* out = (float*)d_out;

    ubK<<<600, 256>>>(obj, qual);
    selT1K<<<BATCH, 256>>>();
    collEvalK<<<600, 256>>>(cls);
    finalK<<<BATCH, 1024>>>(box, cls, anch, out);
}

// round 5
// speedup vs baseline: 1.6548x; 1.1197x over previous
#include <cuda_runtime.h>
#include <cstdint>

#define BATCH 8
#define NA 3
#define NC 80
#define HH 160
#define WW 160
#define HW 25600      // HH*WW
#define NPB 76800     // NA*HW candidates per batch
#define TOPKK 100
#define MTARGET 2048  // E1 target size per batch
#define NBIN 4096
#define CAP 4096

typedef unsigned long long u64;
typedef unsigned int u32;
typedef unsigned char u8;

// ---------------- static device scratch (zero-initialized at load; finalK re-zeros) -------------
__device__ float g_ub[BATCH * NPB];      // sigmoid(obj)*sigmoid(qual) upper bound
__device__ u64  g_keys[BATCH * NPB];     // evaluated score keys per batch (E1 then E2)
__device__ u8   g_cls[BATCH * NPB];      // argmax class per evaluated candidate
__device__ u32  g_ubhist[BATCH * NBIN];  // histogram of ub float bits >> 18
__device__ u32  g_schist[BATCH * NBIN];  // histogram of E1 score bits (key >> 35)
__device__ int  g_cnt1[BATCH];           // E1 count
__device__ int  g_cnt2[BATCH];           // E2 count
__device__ u32  g_T1[BATCH];             // ub bin threshold defining E1
__device__ u32  g_T2[BATCH];             // score bin lower bound for top-100

__device__ __forceinline__ float fsig(float x) { return 1.0f / (1.0f + __expf(-x)); }

// warp-collective: max+argmax over 80 class logits -> exact score key; writes class byte
__device__ __forceinline__ u64 evalCand(const float* __restrict__ cls, int b, int idx, int lane) {
    int a = idx / HW;
    int pix = idx - a * HW;
    const float* cp = cls + (size_t)(b * NA + a) * NC * HW + pix;
    float m = cp[(size_t)lane * HW];
    int c = lane;
    float v = cp[(size_t)(lane + 32) * HW];
    if (v > m) { m = v; c = lane + 32; }                  // strict >: smaller class on tie
    if (lane < 16) {
        float w = cp[(size_t)(lane + 64) * HW];
        if (w > m) { m = w; c = lane + 64; }
    }
#pragma unroll
    for (int off = 16; off; off >>= 1) {
        float om = __shfl_xor_sync(0xffffffffu, m, off);
        int   oc = __shfl_xor_sync(0xffffffffu, c, off);
        if (om > m || (om == m && oc < c)) { m = om; c = oc; }
    }
    float ub = g_ub[b * NPB + idx];
    // IEEE division with denom >= 1  =>  score <= ub bitwise (pruning invariant)
    float score = __fdiv_rn(ub, 1.0f + __expf(-m));
    if (lane == 0) g_cls[b * NPB + idx] = (u8)c;
    return ((u64)__float_as_uint(score) << 17) | (u32)(NPB - 1 - idx);
}

// ---------------- K1: upper bound + per-batch histogram ----------------
__global__ void __launch_bounds__(256) ubK(const float* __restrict__ obj,
                                           const float* __restrict__ qual) {
    __shared__ u32 hist[NBIN];
    for (int j = threadIdx.x; j < NBIN; j += 256) hist[j] = 0;
    __syncthreads();

    int bid = blockIdx.x;
    int b = bid / 75;
    int g0 = b * NPB + (bid - b * 75) * 1024 + threadIdx.x * 4;
    float4 o4 = *reinterpret_cast<const float4*>(obj + g0);
    float4 q4 = *reinterpret_cast<const float4*>(qual + g0);
    float u0 = 1.0f / ((1.0f + __expf(-o4.x)) * (1.0f + __expf(-q4.x)));
    float u1 = 1.0f / ((1.0f + __expf(-o4.y)) * (1.0f + __expf(-q4.y)));
    float u2 = 1.0f / ((1.0f + __expf(-o4.z)) * (1.0f + __expf(-q4.z)));
    float u3 = 1.0f / ((1.0f + __expf(-o4.w)) * (1.0f + __expf(-q4.w)));
    *reinterpret_cast<float4*>(g_ub + g0) = make_float4(u0, u1, u2, u3);

    atomicAdd(&hist[__float_as_uint(u0) >> 18], 1u);
    atomicAdd(&hist[__float_as_uint(u1) >> 18], 1u);
    atomicAdd(&hist[__float_as_uint(u2) >> 18], 1u);
    atomicAdd(&hist[__float_as_uint(u3) >> 18], 1u);
    __syncthreads();

    u32* gh = g_ubhist + b * NBIN;
    for (int j = threadIdx.x; j < NBIN; j += 256) {
        u32 v = hist[j];
        if (v) atomicAdd(&gh[j], v);
    }
}

// ---------------- K2/K4: boundary-bin selection (which=0: ub/MTARGET->T1, which=1: score/TOPKK->T2)
__global__ void __launch_bounds__(256) selK(int which) {
    int b = blockIdx.x, t = threadIdx.x;
    const u32* gh = (which ? g_schist : g_ubhist) + b * NBIN;
    int K = which ? TOPKK : MTARGET;
    __shared__ u32 h[NBIN];
    __shared__ u32 csum[256];
    for (int j = t; j < NBIN; j += 256) h[j] = gh[j];
    __syncthreads();
    u32 s = 0;
#pragma unroll
    for (int q = 0; q < 16; q++) s += h[t * 16 + q];
    csum[t] = s;
    __syncthreads();
    for (int d = 1; d < 256; d <<= 1) {
        u32 v = (t + d < 256) ? csum[t + d] : 0u;
        __syncthreads();
        csum[t] += v;
        __syncthreads();
    }
    u32 above = (t < 255) ? csum[t + 1] : 0u;
    if ((int)csum[t] >= K && (int)above < K) {   // exactly one thread
        u32 cum = above;
        int d;
        for (d = t * 16 + 15;; d--) {
            if ((int)(cum + h[d]) >= K) break;
            cum += h[d];
        }
        if (which) g_T2[b] = (u32)d; else g_T1[b] = (u32)d;
    }
}

// ---------------- K3: collect E1 (block-aggregated) + evaluate + score hist ----------------
__global__ void __launch_bounds__(256) collEvalK(const float* __restrict__ cls) {
    __shared__ int sbuf[1024];
    __shared__ int s_n, s_pos;
    int tid = threadIdx.x;
    if (tid == 0) { s_n = 0; s_pos = 0; }
    __syncthreads();

    int bid = blockIdx.x;
    int b = bid / 75;
    int i0 = (bid - b * 75) * 1024 + tid * 4;
    u32 T1 = g_T1[b];
    float4 u4 = *reinterpret_cast<const float4*>(g_ub + b * NPB + i0);
    float us[4] = {u4.x, u4.y, u4.z, u4.w};
#pragma unroll
    for (int j = 0; j < 4; j++) {
        if ((__float_as_uint(us[j]) >> 18) >= T1) {
            int p = atomicAdd(&s_n, 1);          // shared atomic: cheap
            sbuf[p] = i0 + j;
        }
    }
    __syncthreads();
    if (tid == 0 && s_n) s_pos = atomicAdd(&g_cnt1[b], s_n);   // ONE global atomic per block
    __syncthreads();

    int n = s_n, pos = s_pos;
    int lane = tid & 31, warp = tid >> 5;
    for (int j = warp; j < n; j += 8) {
        u64 key = evalCand(cls, b, sbuf[j], lane);
        if (lane == 0) {
            g_keys[(size_t)b * NPB + pos + j] = key;
            atomicAdd(&g_schist[b * NBIN + (u32)(key >> 35)], 1u);
        }
    }
}

// ---------------- K5: wide E2 — collect+eval pixels with ub bin in [T2, T1) ----------------
__global__ void __launch_bounds__(256) e2K(const float* __restrict__ cls) {
    int bid = blockIdx.x;
    int b = bid / 75;
    u32 T1 = g_T1[b], T2 = g_T2[b];
    if (T2 >= T1) return;                        // common case: no E2 needed, whole block exits

    __shared__ int sbuf[1024];
    __shared__ int s_n, s_pos;
    int tid = threadIdx.x;
    if (tid == 0) { s_n = 0; s_pos = 0; }
    __syncthreads();

    int i0 = (bid - b * 75) * 1024 + tid * 4;
    float4 u4 = *reinterpret_cast<const float4*>(g_ub + b * NPB + i0);
    float us[4] = {u4.x, u4.y, u4.z, u4.w};
#pragma unroll
    for (int j = 0; j < 4; j++) {
        u32 bin = __float_as_uint(us[j]) >> 18;
        if (bin >= T2 && bin < T1) {
            int p = atomicAdd(&s_n, 1);
            sbuf[p] = i0 + j;
        }
    }
    __syncthreads();
    if (tid == 0 && s_n) s_pos = atomicAdd(&g_cnt2[b], s_n);
    __syncthreads();

    int n = s_n, pos = g_cnt1[b] + s_pos;        // append after E1 keys
    int lane = tid & 31, warp = tid >> 5;
    for (int j = warp; j < n; j += 8) {
        u64 key = evalCand(cls, b, sbuf[j], lane);
        if (lane == 0) g_keys[(size_t)b * NPB + pos + j] = key;
    }
}

// ---------------- K6: filter, rank, decode, reset scratch ----------------
__global__ void __launch_bounds__(1024) finalK(const float* __restrict__ box,
                                               const float* __restrict__ anch,
                                               float* __restrict__ out) {
    int b = blockIdx.x, tid = threadIdx.x;
    __shared__ u64 scand[CAP];                   // 32 KB (aliased as hist in slow path)
    __shared__ u64 wkeys[TOPKK];
    __shared__ u32 csum[1024];                   // slow path only
    __shared__ int s_cnt, s_d, s_locked, s_bucket;

    int M = g_cnt1[b] + g_cnt2[b];
    u32 T2v = g_T2[b];
    const u64* keys = g_keys + (size_t)b * NPB;

    // ---- filter keys with score bin >= T2 (>=100 exist by construction of T2) ----
    if (tid == 0) s_cnt = 0;
    __syncthreads();
    for (int j = tid; j < M; j += 1024) {
        u64 k = keys[j];
        if ((u32)(k >> 35) >= T2v) {
            int pos = atomicAdd(&s_cnt, 1);
            if (pos < CAP) scand[pos] = k;
        }
    }
    __syncthreads();
    int C = s_cnt;

    if (C > CAP) {
        // exact slow path: 12-bit radix refinement over all M keys (keys < 2^49)
        u32* hist = reinterpret_cast<u32*>(scand);
        u64 prefixVal = 0;
        int locked = 0, shift = 35, bucket = 0;
        for (int lvl = 0; lvl < 3; lvl++) {
            shift = 35 - 12 * lvl;
            __syncthreads();
            for (int j = tid; j < NBIN; j += 1024) hist[j] = 0;
            __syncthreads();
            u64 maskAbove = ~((((u64)1) << (shift + 12)) - 1);
            for (int j = tid; j < M; j += 1024) {
                u64 k = keys[j];
                if ((k & maskAbove) == prefixVal)
                    atomicAdd(&hist[(u32)(k >> shift) & (NBIN - 1)], 1u);
            }
            __syncthreads();
            u32 ss = 0;
#pragma unroll
            for (int q = 0; q < 4; q++) ss += hist[tid * 4 + q];
            csum[tid] = ss;
            __syncthreads();
            for (int d = 1; d < 1024; d <<= 1) {
                u32 v = (tid + d < 1024) ? csum[tid + d] : 0u;
                __syncthreads();
                csum[tid] += v;
                __syncthreads();
            }
            u32 above = (tid < 1023) ? csum[tid + 1] : 0u;
            if (locked + (int)csum[tid] >= TOPKK && locked + (int)above < TOPKK) {
                u32 cum = above;
                int d;
                for (d = tid * 4 + 3;; d--) {
                    if (locked + (int)(cum + hist[d]) >= TOPKK) break;
                    cum += hist[d];
                }
                s_d = d; s_locked = locked + (int)cum; s_bucket = (int)hist[d];
            }
            __syncthreads();
            locked = s_locked;
            prefixVal |= ((u64)s_d) << shift;
            bucket = s_bucket;
            __syncthreads();
            if (locked + bucket <= CAP) break;   // guaranteed by shift=11 (bucket <= 2048)
        }
        if (tid == 0) s_cnt = 0;
        __syncthreads();
        u64 thr = prefixVal >> shift;
        for (int j = tid; j < M; j += 1024) {
            u64 k = keys[j];
            if ((k >> shift) >= thr) {
                int pos = atomicAdd(&s_cnt, 1);
                scand[pos] = k;
            }
        }
        __syncthreads();
        C = s_cnt;
    }

    // ---- rank by counting (keys are distinct -> exact permutation, no syncs inside) ----
    for (int i = tid; i < C; i += 1024) {
        u64 k = scand[i];
        int r = 0;
        for (int j = 0; j < C; j++) r += (scand[j] > k);
        if (r < TOPKK) wkeys[r] = k;
    }
    __syncthreads();

    // ---- decode winners: one thread per rank (class byte precomputed in eval) ----
    if (tid < TOPKK) {
        u64 k = wkeys[tid];
        u32 sb = (u32)(k >> 17);
        int idx = NPB - 1 - (int)(k & 0x1FFFFu);
        int a = idx / HW;
        int pix = idx - a * HW;
        int y = pix / WW;
        int x = pix - y * WW;
        int c = (int)g_cls[b * NPB + idx];

        const float* bp = box + (size_t)(b * NA + a) * 4 * HW + pix;
        float tx = bp[0];
        float ty = bp[(size_t)HW];
        float tw = bp[2 * (size_t)HW];
        float th = bp[3 * (size_t)HW];
        float aw = anch[a * 2 + 0];
        float ah = anch[a * 2 + 1];
        float cx = (fsig(tx) + (float)x) / (float)WW;
        float cy = (fsig(ty) + (float)y) / (float)HH;
        // faithful softplus: relu(x) + log1p(exp(-|x|))
        float spw = fmaxf(tw, 0.0f) + log1pf(__expf(-fabsf(tw)));
        float sph = fmaxf(th, 0.0f) + log1pf(__expf(-fabsf(th)));
        float* o = out + ((size_t)b * TOPKK + tid) * 6;
        o[0] = __uint_as_float(sb);
        o[1] = (float)c;
        o[2] = cx;
        o[3] = cy;
        o[4] = aw * spw;
        o[5] = ah * sph;
    }

    // ---- reset scratch for the next replay (device globals start zeroed on load) ----
    __syncthreads();
    u32* uh = g_ubhist + b * NBIN;
    u32* sh = g_schist + b * NBIN;
    for (int j = tid; j < NBIN; j += 1024) { uh[j] = 0; sh[j] = 0; }
    if (tid == 0) { g_cnt1[b] = 0; g_cnt2[b] = 0; }
}

// ---------------- launch ----------------
extern "C" void kernel_launch(void* const* d_in, const int* in_sizes, int n_in,
                              void* d_out, int out_size) {
    const float* box  = (const float*)d_in[0];
    const float* obj  = (const float*)d_in[1];
    const float* qual = (const float*)d_in[2];
    const float* cls  = (const float*)d_in[3];
    const float* anch = (const float*)d_in[4];
    int seen = 0;
    for (int i = 0; i < n_in; i++) {
        int s = in_sizes[i];
        if (s == BATCH * NA * 4 * HW) box = (const float*)d_in[i];
        else if (s == BATCH * NA * NC * HW) cls = (const float*)d_in[i];
        else if (s == NA * 2) anch = (const float*)d_in[i];
        else if (s == BATCH * NA * HW) {
            if (seen == 0) obj = (const float*)d_in[i];
            else qual = (const float*)d_in[i];
            seen++;
        }
    }
    float* out = (float*)d_out;

    ubK<<<600, 256>>>(obj, qual);
    selK<<<BATCH, 256>>>(0);
    collEvalK<<<600, 256>>>(cls);
    selK<<<BATCH, 256>>>(1);
    e2K<<<600, 256>>>(cls);
    finalK<<<BATCH, 1024>>>(box, anch, out);
}

// round 6
// speedup vs baseline: 2.5317x; 1.5299x over previous
#include <cuda_runtime.h>
#include <cstdint>

#define BATCH 8
#define NA 3
#define NC 80
#define HH 160
#define WW 160
#define HW 25600      // HH*WW
#define NPB 76800     // NA*HW candidates per batch
#define TOPKK 100
#define MTARGET 768   // E1 target size per batch (e2K covers any shortfall exactly)
#define NBIN 4096
#define CAP 4096

typedef unsigned long long u64;
typedef unsigned int u32;
typedef unsigned char u8;

// ---------------- static device scratch (zero-initialized at load; finalK re-zeros) -------------
__device__ float g_ub[BATCH * NPB];      // sigmoid(obj)*sigmoid(qual) upper bound
__device__ u64  g_keys[BATCH * NPB];     // evaluated score keys per batch (E1 then E2)
__device__ u8   g_cls[BATCH * NPB];      // argmax class per evaluated candidate
__device__ u32  g_ubhist[BATCH * NBIN];  // histogram of ub float bits >> 18
__device__ u32  g_schist[BATCH * NBIN];  // histogram of E1 score bits (key >> 35)
__device__ int  g_cnt1[BATCH];           // E1 count
__device__ int  g_cnt2[BATCH];           // E2 count
__device__ u32  g_T1[BATCH];             // ub bin threshold defining E1
__device__ u32  g_T2[BATCH];             // score bin lower bound for top-100
__device__ int  g_tick1[BATCH];          // ubK per-batch completion tickets
__device__ int  g_tick2[BATCH];          // collEvalK per-batch completion tickets

__device__ __forceinline__ float fsig(float x) { return 1.0f / (1.0f + __expf(-x)); }

// 256-thread selection: boundary bin (from top) where cumulative count reaches K.
// All 256 threads of the calling block must enter. h: NBIN smem, csum: 256 smem.
__device__ void selectBin(const u32* __restrict__ gh, int K, u32* outT,
                          u32* h, u32* csum) {
    int t = threadIdx.x;
    for (int j = t; j < NBIN; j += 256) h[j] = gh[j];
    __syncthreads();
    u32 s = 0;
#pragma unroll
    for (int q = 0; q < 16; q++) s += h[t * 16 + q];
    csum[t] = s;
    __syncthreads();
    for (int d = 1; d < 256; d <<= 1) {           // inclusive suffix scan
        u32 v = (t + d < 256) ? csum[t + d] : 0u;
        __syncthreads();
        csum[t] += v;
        __syncthreads();
    }
    u32 above = (t < 255) ? csum[t + 1] : 0u;
    if ((int)csum[t] >= K && (int)above < K) {    // exactly one thread
        u32 cum = above;
        int d;
        for (d = t * 16 + 15;; d--) {
            if ((int)(cum + h[d]) >= K) break;
            cum += h[d];
        }
        *outT = (u32)d;
    }
}

// warp-collective: max+argmax over 80 class logits -> exact score key; writes class byte
__device__ __forceinline__ u64 evalCand(const float* __restrict__ cls, int b, int idx, int lane) {
    int a = idx / HW;
    int pix = idx - a * HW;
    const float* cp = cls + (size_t)(b * NA + a) * NC * HW + pix;
    float m = cp[(size_t)lane * HW];
    int c = lane;
    float v = cp[(size_t)(lane + 32) * HW];
    if (v > m) { m = v; c = lane + 32; }                  // strict >: smaller class on tie
    if (lane < 16) {
        float w = cp[(size_t)(lane + 64) * HW];
        if (w > m) { m = w; c = lane + 64; }
    }
#pragma unroll
    for (int off = 16; off; off >>= 1) {
        float om = __shfl_xor_sync(0xffffffffu, m, off);
        int   oc = __shfl_xor_sync(0xffffffffu, c, off);
        if (om > m || (om == m && oc < c)) { m = om; c = oc; }
    }
    float ub = g_ub[b * NPB + idx];
    // IEEE division with denom >= 1  =>  score <= ub bitwise (pruning invariant)
    float score = __fdiv_rn(ub, 1.0f + __expf(-m));
    if (lane == 0) g_cls[b * NPB + idx] = (u8)c;
    return ((u64)__float_as_uint(score) << 17) | (u32)(NPB - 1 - idx);
}

// ---------------- K1: ub + per-batch histogram; last block per batch selects T1 ----------------
__global__ void __launch_bounds__(256) ubK(const float* __restrict__ obj,
                                           const float* __restrict__ qual) {
    __shared__ u32 hist[NBIN];
    __shared__ u32 csum[256];
    __shared__ int s_last;
    for (int j = threadIdx.x; j < NBIN; j += 256) hist[j] = 0;
    __syncthreads();

    int bid = blockIdx.x;
    int b = bid / 75;
    int g0 = b * NPB + (bid - b * 75) * 1024 + threadIdx.x * 4;
    float4 o4 = *reinterpret_cast<const float4*>(obj + g0);
    float4 q4 = *reinterpret_cast<const float4*>(qual + g0);
    float u0 = 1.0f / ((1.0f + __expf(-o4.x)) * (1.0f + __expf(-q4.x)));
    float u1 = 1.0f / ((1.0f + __expf(-o4.y)) * (1.0f + __expf(-q4.y)));
    float u2 = 1.0f / ((1.0f + __expf(-o4.z)) * (1.0f + __expf(-q4.z)));
    float u3 = 1.0f / ((1.0f + __expf(-o4.w)) * (1.0f + __expf(-q4.w)));
    *reinterpret_cast<float4*>(g_ub + g0) = make_float4(u0, u1, u2, u3);

    atomicAdd(&hist[__float_as_uint(u0) >> 18], 1u);
    atomicAdd(&hist[__float_as_uint(u1) >> 18], 1u);
    atomicAdd(&hist[__float_as_uint(u2) >> 18], 1u);
    atomicAdd(&hist[__float_as_uint(u3) >> 18], 1u);
    __syncthreads();

    u32* gh = g_ubhist + b * NBIN;
    for (int j = threadIdx.x; j < NBIN; j += 256) {
        u32 v = hist[j];
        if (v) atomicAdd(&gh[j], v);
    }
    __syncthreads();
    if (threadIdx.x == 0) {
        __threadfence();
        s_last = (atomicAdd(&g_tick1[b], 1) == 74);
    }
    __syncthreads();
    if (s_last) selectBin(gh, MTARGET, &g_T1[b], hist, csum);   // hist hot in L2
}

// ---------------- K2: collect E1 + evaluate + score hist; last block per batch selects T2 --------
__global__ void __launch_bounds__(256) collEvalK(const float* __restrict__ cls) {
    __shared__ int sbuf[1024];
    __shared__ u32 selh[NBIN];
    __shared__ u32 csum[256];
    __shared__ int s_n, s_pos, s_last;
    int tid = threadIdx.x;
    if (tid == 0) { s_n = 0; s_pos = 0; }
    __syncthreads();

    int bid = blockIdx.x;
    int b = bid / 75;
    int i0 = (bid - b * 75) * 1024 + tid * 4;
    u32 T1 = g_T1[b];
    float4 u4 = *reinterpret_cast<const float4*>(g_ub + b * NPB + i0);
    float us[4] = {u4.x, u4.y, u4.z, u4.w};
#pragma unroll
    for (int j = 0; j < 4; j++) {
        if ((__float_as_uint(us[j]) >> 18) >= T1) {
            int p = atomicAdd(&s_n, 1);          // shared atomic: cheap
            sbuf[p] = i0 + j;
        }
    }
    __syncthreads();
    if (tid == 0 && s_n) s_pos = atomicAdd(&g_cnt1[b], s_n);   // ONE global atomic per block
    __syncthreads();

    int n = s_n, pos = s_pos;
    int lane = tid & 31, warp = tid >> 5;
    for (int j = warp; j < n; j += 8) {
        u64 key = evalCand(cls, b, sbuf[j], lane);
        if (lane == 0) {
            g_keys[(size_t)b * NPB + pos + j] = key;
            atomicAdd(&g_schist[b * NBIN + (u32)(key >> 35)], 1u);
        }
    }
    __syncthreads();
    if (tid == 0) {
        __threadfence();
        s_last = (atomicAdd(&g_tick2[b], 1) == 74);
    }
    __syncthreads();
    if (s_last) selectBin(g_schist + b * NBIN, TOPKK, &g_T2[b], selh, csum);
}

// ---------------- K3: wide E2 — collect+eval pixels with ub bin in [T2, T1) ----------------
__global__ void __launch_bounds__(256) e2K(const float* __restrict__ cls) {
    int bid = blockIdx.x;
    int b = bid / 75;
    u32 T1 = g_T1[b], T2 = g_T2[b];
    if (T2 >= T1) return;                        // common case: whole block exits immediately

    __shared__ int sbuf[1024];
    __shared__ int s_n, s_pos;
    int tid = threadIdx.x;
    if (tid == 0) { s_n = 0; s_pos = 0; }
    __syncthreads();

    int i0 = (bid - b * 75) * 1024 + tid * 4;
    float4 u4 = *reinterpret_cast<const float4*>(g_ub + b * NPB + i0);
    float us[4] = {u4.x, u4.y, u4.z, u4.w};
#pragma unroll
    for (int j = 0; j < 4; j++) {
        u32 bin = __float_as_uint(us[j]) >> 18;
        if (bin >= T2 && bin < T1) {
            int p = atomicAdd(&s_n, 1);
            sbuf[p] = i0 + j;
        }
    }
    __syncthreads();
    if (tid == 0 && s_n) s_pos = atomicAdd(&g_cnt2[b], s_n);
    __syncthreads();

    int n = s_n, pos = g_cnt1[b] + s_pos;        // append after E1 keys
    int lane = tid & 31, warp = tid >> 5;
    for (int j = warp; j < n; j += 8) {
        u64 key = evalCand(cls, b, sbuf[j], lane);
        if (lane == 0) g_keys[(size_t)b * NPB + pos + j] = key;
    }
}

// ---------------- K4: filter, rank, decode, reset scratch ----------------
__global__ void __launch_bounds__(1024) finalK(const float* __restrict__ box,
                                               const float* __restrict__ anch,
                                               float* __restrict__ out) {
    int b = blockIdx.x, tid = threadIdx.x;
    __shared__ u64 scand[CAP];                   // 32 KB (aliased as hist in slow path)
    __shared__ u64 wkeys[TOPKK];
    __shared__ u32 csum[1024];                   // slow path only
    __shared__ int s_cnt, s_d, s_locked, s_bucket;

    int M = g_cnt1[b] + g_cnt2[b];
    u32 T2v = g_T2[b];
    const u64* keys = g_keys + (size_t)b * NPB;

    // ---- filter keys with score bin >= T2 (>=100 exist by construction of T2) ----
    if (tid == 0) s_cnt = 0;
    __syncthreads();
    for (int j = tid; j < M; j += 1024) {
        u64 k = keys[j];
        if ((u32)(k >> 35) >= T2v) {
            int pos = atomicAdd(&s_cnt, 1);
            if (pos < CAP) scand[pos] = k;
        }
    }
    __syncthreads();
    int C = s_cnt;

    if (C > CAP) {
        // exact slow path: 12-bit radix refinement over all M keys (keys < 2^49)
        u32* hist = reinterpret_cast<u32*>(scand);
        u64 prefixVal = 0;
        int locked = 0, shift = 35, bucket = 0;
        for (int lvl = 0; lvl < 3; lvl++) {
            shift = 35 - 12 * lvl;
            __syncthreads();
            for (int j = tid; j < NBIN; j += 1024) hist[j] = 0;
            __syncthreads();
            u64 maskAbove = ~((((u64)1) << (shift + 12)) - 1);
            for (int j = tid; j < M; j += 1024) {
                u64 k = keys[j];
                if ((k & maskAbove) == prefixVal)
                    atomicAdd(&hist[(u32)(k >> shift) & (NBIN - 1)], 1u);
            }
            __syncthreads();
            u32 ss = 0;
#pragma unroll
            for (int q = 0; q < 4; q++) ss += hist[tid * 4 + q];
            csum[tid] = ss;
            __syncthreads();
            for (int d = 1; d < 1024; d <<= 1) {
                u32 v = (tid + d < 1024) ? csum[tid + d] : 0u;
                __syncthreads();
                csum[tid] += v;
                __syncthreads();
            }
            u32 above = (tid < 1023) ? csum[tid + 1] : 0u;
            if (locked + (int)csum[tid] >= TOPKK && locked + (int)above < TOPKK) {
                u32 cum = above;
                int d;
                for (d = tid * 4 + 3;; d--) {
                    if (locked + (int)(cum + hist[d]) >= TOPKK) break;
                    cum += hist[d];
                }
                s_d = d; s_locked = locked + (int)cum; s_bucket = (int)hist[d];
            }
            __syncthreads();
            locked = s_locked;
            prefixVal |= ((u64)s_d) << shift;
            bucket = s_bucket;
            __syncthreads();
            if (locked + bucket <= CAP) break;   // guaranteed by shift=11 (bucket <= 2048)
        }
        if (tid == 0) s_cnt = 0;
        __syncthreads();
        u64 thr = prefixVal >> shift;
        for (int j = tid; j < M; j += 1024) {
            u64 k = keys[j];
            if ((k >> shift) >= thr) {
                int pos = atomicAdd(&s_cnt, 1);
                scand[pos] = k;
            }
        }
        __syncthreads();
        C = s_cnt;
    }

    // ---- rank by counting (keys distinct -> exact permutation, no syncs inside) ----
    for (int i = tid; i < C; i += 1024) {
        u64 k = scand[i];
        int r = 0;
        for (int j = 0; j < C; j++) r += (scand[j] > k);
        if (r < TOPKK) wkeys[r] = k;
    }
    __syncthreads();

    // ---- decode winners: one thread per rank (class byte precomputed in eval) ----
    if (tid < TOPKK) {
        u64 k = wkeys[tid];
        u32 sb = (u32)(k >> 17);
        int idx = NPB - 1 - (int)(k & 0x1FFFFu);
        int a = idx / HW;
        int pix = idx - a * HW;
        int y = pix / WW;
        int x = pix - y * WW;
        int c = (int)g_cls[b * NPB + idx];

        const float* bp = box + (size_t)(b * NA + a) * 4 * HW + pix;
        float tx = bp[0];
        float ty = bp[(size_t)HW];
        float tw = bp[2 * (size_t)HW];
        float th = bp[3 * (size_t)HW];
        float aw = anch[a * 2 + 0];
        float ah = anch[a * 2 + 1];
        float cx = (fsig(tx) + (float)x) / (float)WW;
        float cy = (fsig(ty) + (float)y) / (float)HH;
        // faithful softplus: relu(x) + log1p(exp(-|x|))
        float spw = fmaxf(tw, 0.0f) + log1pf(__expf(-fabsf(tw)));
        float sph = fmaxf(th, 0.0f) + log1pf(__expf(-fabsf(th)));
        float* o = out + ((size_t)b * TOPKK + tid) * 6;
        o[0] = __uint_as_float(sb);
        o[1] = (float)c;
        o[2] = cx;
        o[3] = cy;
        o[4] = aw * spw;
        o[5] = ah * sph;
    }

    // ---- reset scratch for the next replay (device globals start zeroed on load) ----
    __syncthreads();
    u32* uh = g_ubhist + b * NBIN;
    u32* sh = g_schist + b * NBIN;
    for (int j = tid; j < NBIN; j += 1024) { uh[j] = 0; sh[j] = 0; }
    if (tid == 0) {
        g_cnt1[b] = 0; g_cnt2[b] = 0;
        g_tick1[b] = 0; g_tick2[b] = 0;
    }
}

// ---------------- launch ----------------
extern "C" void kernel_launch(void* const* d_in, const int* in_sizes, int n_in,
                              void* d_out, int out_size) {
    const float* box  = (const float*)d_in[0];
    const float* obj  = (const float*)d_in[1];
    const float* qual = (const float*)d_in[2];
    const float* cls  = (const float*)d_in[3];
    const float* anch = (const float*)d_in[4];
    int seen = 0;
    for (int i = 0; i < n_in; i++) {
        int s = in_sizes[i];
        if (s == BATCH * NA * 4 * HW) box = (const float*)d_in[i];
        else if (s == BATCH * NA * NC * HW) cls = (const float*)d_in[i];
        else if (s == NA * 2) anch = (const float*)d_in[i];
        else if (s == BATCH * NA * HW) {
            if (seen == 0) obj = (const float*)d_in[i];
            else qual = (const float*)d_in[i];
            seen++;
        }
    }
    float* out = (float*)d_out;

    ubK<<<600, 256>>>(obj, qual);
    collEvalK<<<600, 256>>>(cls);
    e2K<<<600, 256>>>(cls);
    finalK<<<BATCH, 1024>>>(box, anch, out);
}